// round 1
// baseline (speedup 1.0000x reference)
#include <cuda_runtime.h>
#include <math.h>

#define Bsz  2048
#define Nn_  200
#define Rr   256
#define Ee   256
#define Hh   512
#define FILLV (-10000.0f)

// ---------------- device scratch (no allocation allowed) ----------------
__device__ float g_WmT[256 * 256];        // Wm^T [e][r]
__device__ float g_Wkm[256 * 256];        // Wk @ Wm^T  [e][r]
__device__ float g_Wgfull[512 * 256];     // [Wg_top ; Wm @ Wg_bot]
__device__ float g_Wmt[256 * 256];        // Wm @ Wt
__device__ float g_cat[Bsz * 512];        // [:,0:256]=m_init  [:,256:512]=c
__device__ float g_v[Bsz * 256];
__device__ float g_gg[Bsz * 256];
__device__ float g_mo[Bsz * 256];
__device__ float g_y[Bsz * 512];
__device__ int   g_mask_mode;             // 0=byte(bool) 1=int32 2=float32

// ---------------- tiny prep kernels ----------------
__global__ void transpose_wm(const float* __restrict__ Wm) {
    int e = blockIdx.x, r = threadIdx.x;
    g_WmT[e * 256 + r] = Wm[r * 256 + e];
}

__global__ void copy_wg_top(const float* __restrict__ Wg) {
    int i = blockIdx.x * 1024 + threadIdx.x;   // grid 64 x 1024 = 65536
    g_Wgfull[i] = Wg[i];
}

// Byte-sniff the hist_mask buffer layout.
__global__ void detect_mask(const unsigned char* __restrict__ p) {
    __shared__ int flags[4];
    int t = threadIdx.x;
    if (t < 4) flags[t] = 0;
    __syncthreads();
    int loc = 0;
    const int total = Bsz * Nn_;              // safe: buffer >= B*N bytes in all layouts
    for (int i = t; i < total; i += blockDim.x)
        if (p[i]) loc = 1;
    if (loc) atomicOr(&flags[t & 3], 1);      // stride 256 => i&3 == t&3 constant
    __syncthreads();
    if (t == 0) {
        int mode;
        if (flags[1]) mode = 0;               // bytes at pos%4==1 nonzero -> bool bytes
        else if (flags[2] || flags[3]) mode = 2; // only high bytes -> float32 1.0f pattern
        else if (flags[0]) mode = 1;          // only pos%4==0 -> int32 {0,1}
        else mode = 0;                        // all zero: any interpretation works
        g_mask_mode = mode;
    }
}

// ---------------- generic fp32 tiled GEMM: C[MxN] = A[MxK] @ B[KxN] ----------------
// Tiles: 64x64, BK=16, 256 threads, 4x4 register tile per thread.
// M,N multiples of 64; K multiple of 16 (all our shapes qualify).
// EPI 0: C = acc (+bias).   EPI 2: m_out gate epilogue.
template <int EPI>
__global__ void __launch_bounds__(256) gemm_k(
    const float* __restrict__ A, int lda,
    const float* __restrict__ B, int ldb,
    float* __restrict__ C, int ldc,
    int K,
    const float* __restrict__ bias,
    const float* __restrict__ gg,            // EPI2: gate pre-activation [M x 256]
    const float* __restrict__ mi, int ldmi)  // EPI2: m_init
{
    __shared__ float Ast[16][68];   // A transposed in smem: [k][m]
    __shared__ float Bs[16][68];    // [k][n]
    const int tid = threadIdx.x;
    const int m0 = blockIdx.y * 64;
    const int n0 = blockIdx.x * 64;
    const int tx = tid & 15, ty = tid >> 4;
    const int arow = tid >> 2, ac4 = (tid & 3) * 4;
    const int brow = tid >> 4, bc4 = (tid & 15) * 4;

    float acc[4][4];
#pragma unroll
    for (int i = 0; i < 4; i++)
#pragma unroll
        for (int j = 0; j < 4; j++) acc[i][j] = 0.f;

    const float* Ag = A + (size_t)(m0 + arow) * lda + ac4;
    const float* Bg = B + (size_t)brow * ldb + n0 + bc4;

    for (int kb = 0; kb < K; kb += 16) {
        float4 avv = *(const float4*)(Ag + kb);
        float4 bvv = *(const float4*)(Bg + (size_t)kb * ldb);
        __syncthreads();
        Ast[ac4 + 0][arow] = avv.x;
        Ast[ac4 + 1][arow] = avv.y;
        Ast[ac4 + 2][arow] = avv.z;
        Ast[ac4 + 3][arow] = avv.w;
        *(float4*)&Bs[brow][bc4] = bvv;
        __syncthreads();
#pragma unroll
        for (int k = 0; k < 16; k++) {
            float4 a = *(const float4*)&Ast[k][ty * 4];
            float4 b = *(const float4*)&Bs[k][tx * 4];
            acc[0][0] = fmaf(a.x, b.x, acc[0][0]);
            acc[0][1] = fmaf(a.x, b.y, acc[0][1]);
            acc[0][2] = fmaf(a.x, b.z, acc[0][2]);
            acc[0][3] = fmaf(a.x, b.w, acc[0][3]);
            acc[1][0] = fmaf(a.y, b.x, acc[1][0]);
            acc[1][1] = fmaf(a.y, b.y, acc[1][1]);
            acc[1][2] = fmaf(a.y, b.z, acc[1][2]);
            acc[1][3] = fmaf(a.y, b.w, acc[1][3]);
            acc[2][0] = fmaf(a.z, b.x, acc[2][0]);
            acc[2][1] = fmaf(a.z, b.y, acc[2][1]);
            acc[2][2] = fmaf(a.z, b.z, acc[2][2]);
            acc[2][3] = fmaf(a.z, b.w, acc[2][3]);
            acc[3][0] = fmaf(a.w, b.x, acc[3][0]);
            acc[3][1] = fmaf(a.w, b.y, acc[3][1]);
            acc[3][2] = fmaf(a.w, b.z, acc[3][2]);
            acc[3][3] = fmaf(a.w, b.w, acc[3][3]);
        }
    }

#pragma unroll
    for (int i = 0; i < 4; i++) {
        int gm = m0 + ty * 4 + i;
#pragma unroll
        for (int j = 0; j < 4; j++) {
            int gn = n0 + tx * 4 + j;
            float v = acc[i][j];
            if (EPI == 0) {
                if (bias) v += bias[gn];
                C[(size_t)gm * ldc + gn] = v;
            } else {
                float ggv = gg[(size_t)gm * 256 + gn];
                float g = 1.f / (1.f + expf(-ggv));
                float th = tanhf(v + bias[gn]);
                C[(size_t)gm * ldc + gn] = g * th + (1.f - g) * mi[(size_t)gm * ldmi + gn];
            }
        }
    }
}

// ---------------- streaming attention: one CTA per batch ----------------
// smem tile: nb_rel[b] (200x256 fp32 = 200KB), single HBM pass.
__global__ void __launch_bounds__(256) attn_k(
    const float* __restrict__ nb_rel,
    const float* __restrict__ delta_t,
    const void*  __restrict__ maskp,
    const float* __restrict__ vglob,
    const float* __restrict__ lgam,
    float* __restrict__ cat)
{
    extern __shared__ float TILE[];          // 51200 floats
    __shared__ float SV[256];
    __shared__ float SA[256];                // attn scores -> softmax weights
    __shared__ float RED[256];
    __shared__ int   IRED[256];
    const int t = threadIdx.x;
    const int b = blockIdx.x;

    // async tile load (12800 float4 / 256 threads = 50 each)
    const float4* g4 = (const float4*)(nb_rel + (size_t)b * Nn_ * Rr);
    float4* s4 = (float4*)TILE;
#pragma unroll
    for (int i = 0; i < 50; i++) {
        unsigned sa = (unsigned)__cvta_generic_to_shared(s4 + t + i * 256);
        asm volatile("cp.async.cg.shared.global [%0], [%1], 16;" ::"r"(sa),
                     "l"(g4 + t + i * 256) : "memory");
    }
    asm volatile("cp.async.commit_group;" ::: "memory");

    SV[t] = vglob[(size_t)b * 256 + t];
    float gamma = expf(lgam[0]);

    asm volatile("cp.async.wait_group 0;" ::: "memory");
    __syncthreads();

    // attn_sem[n] = dot(tile[n,:], v)/sqrt(E)  — one warp per row group
    const int w = t >> 5, l = t & 31;
    for (int ni = 0; ni < 25; ni++) {
        int n = w * 25 + ni;
        float s = 0.f;
#pragma unroll
        for (int k = 0; k < 8; k++)
            s = fmaf(TILE[n * 256 + l + 32 * k], SV[l + 32 * k], s);
#pragma unroll
        for (int o = 16; o > 0; o >>= 1) s += __shfl_down_sync(0xffffffffu, s, o);
        if (l == 0) SA[n] = s * 0.0625f;     // 1/sqrt(256)
    }
    __syncthreads();

    // mask + decay + softmax
    const int mode = g_mask_mode;
    int m = 0;
    float av = FILLV;
    if (t < Nn_) {
        size_t mi = (size_t)b * Nn_ + t;
        if (mode == 0)      m = ((const unsigned char*)maskp)[mi] != 0;
        else if (mode == 1) m = ((const int*)maskp)[mi] != 0;
        else                m = (((const float*)maskp)[mi] != 0.f);
        if (m) {
            float term = fmaxf(-gamma * fmaxf(delta_t[mi], 0.f), -10.f);
            av = SA[t] + term;
        }
    }
    IRED[t] = m;
    __syncthreads();
    for (int s = 128; s > 0; s >>= 1) { if (t < s) IRED[t] |= IRED[t + s]; __syncthreads(); }
    int anyv = IRED[0];
    __syncthreads();
    if (!anyv && t < Nn_) av = 0.f;          // all-masked row -> uniform softmax

    RED[t] = av;
    __syncthreads();
    for (int s = 128; s > 0; s >>= 1) { if (t < s) RED[t] = fmaxf(RED[t], RED[t + s]); __syncthreads(); }
    float mx = RED[0];
    __syncthreads();
    float ex = (t < Nn_) ? expf(av - mx) : 0.f;
    RED[t] = ex;
    __syncthreads();
    for (int s = 128; s > 0; s >>= 1) { if (t < s) RED[t] += RED[t + s]; __syncthreads(); }
    float inv = 1.f / RED[0];
    __syncthreads();
    if (t < Nn_) SA[t] = ex * inv;
    __syncthreads();

    // c[r] = sum_n w[n] * tile[n][r]
    float c0 = 0.f, c1 = 0.f;
#pragma unroll 4
    for (int n = 0; n < Nn_; n += 2) {
        c0 = fmaf(SA[n],     TILE[n * 256 + t],       c0);
        c1 = fmaf(SA[n + 1], TILE[(n + 1) * 256 + t], c1);
    }
    cat[(size_t)b * 512 + 256 + t] = c0 + c1;
}

// ---------------- layernorm over H=512, one block per batch row ----------------
__global__ void __launch_bounds__(256) ln_k(
    const float* __restrict__ y, const float* __restrict__ g,
    const float* __restrict__ bta, float* __restrict__ out)
{
    __shared__ float RS[256], RQ[256];
    const int t = threadIdx.x, b = blockIdx.x;
    float a = y[(size_t)b * 512 + t];
    float c = y[(size_t)b * 512 + 256 + t];
    RS[t] = a + c;
    RQ[t] = a * a + c * c;
    __syncthreads();
    for (int s = 128; s > 0; s >>= 1) {
        if (t < s) { RS[t] += RS[t + s]; RQ[t] += RQ[t + s]; }
        __syncthreads();
    }
    float mu = RS[0] * (1.f / 512.f);
    float var = RQ[0] * (1.f / 512.f) - mu * mu;
    float inv = rsqrtf(var + 1e-5f);
    out[(size_t)b * 512 + t]       = (a - mu) * inv * g[t] + bta[t];
    out[(size_t)b * 512 + 256 + t] = (c - mu) * inv * g[t + 256] + bta[t + 256];
}

// ---------------- launch ----------------
extern "C" void kernel_launch(void* const* d_in, const int* in_sizes, int n_in,
                              void* d_out, int out_size) {
    const float* nb_rel  = (const float*)d_in[0];
    const float* delta_t = (const float*)d_in[1];
    const float* r_emb   = (const float*)d_in[2];
    const void*  maskp   = d_in[3];
    const float* Wi = (const float*)d_in[4];
    const float* bi = (const float*)d_in[5];
    const float* Wm = (const float*)d_in[6];
    const float* Wk = (const float*)d_in[7];
    const float* lg = (const float*)d_in[8];
    const float* Wg = (const float*)d_in[9];
    const float* bg = (const float*)d_in[10];
    const float* Wt = (const float*)d_in[11];
    const float* bt = (const float*)d_in[12];
    const float* Wo = (const float*)d_in[13];
    const float* bo = (const float*)d_in[14];
    const float* lng = (const float*)d_in[15];
    const float* lnb = (const float*)d_in[16];
    float* out = (float*)d_out;

    float *WmT, *Wkm, *Wgf, *Wmt, *cat, *vb, *ggb, *mob, *yb;
    cudaGetSymbolAddress((void**)&WmT, g_WmT);
    cudaGetSymbolAddress((void**)&Wkm, g_Wkm);
    cudaGetSymbolAddress((void**)&Wgf, g_Wgfull);
    cudaGetSymbolAddress((void**)&Wmt, g_Wmt);
    cudaGetSymbolAddress((void**)&cat, g_cat);
    cudaGetSymbolAddress((void**)&vb,  g_v);
    cudaGetSymbolAddress((void**)&ggb, g_gg);
    cudaGetSymbolAddress((void**)&mob, g_mo);
    cudaGetSymbolAddress((void**)&yb,  g_y);

    cudaFuncSetAttribute(attn_k, cudaFuncAttributeMaxDynamicSharedMemorySize, 204800);

    // prep
    transpose_wm<<<256, 256>>>(Wm);
    copy_wg_top<<<64, 1024>>>(Wg);
    detect_mask<<<1, 256>>>((const unsigned char*)maskp);

    // folded-weight precomputes (256x256x256 each)
    dim3 g44(4, 4);
    gemm_k<0><<<g44, 256>>>(Wk, 256, WmT, 256, Wkm, 256, 256, nullptr, nullptr, nullptr, 0);
    gemm_k<0><<<g44, 256>>>(Wm, 256, Wg + 65536, 256, Wgf + 65536, 256, 256, nullptr, nullptr, nullptr, 0);
    gemm_k<0><<<g44, 256>>>(Wm, 256, Wt, 256, Wmt, 256, 256, nullptr, nullptr, nullptr, 0);

    // main chain
    dim3 gB256(4, 32);   // N=256, M=2048
    dim3 gB512(8, 32);   // N=512, M=2048
    // m_init -> cat[:,0:256]
    gemm_k<0><<<gB256, 256>>>(r_emb, 256, Wi, 256, cat, 512, 256, bi, nullptr, nullptr, 0);
    // v = m_init @ Wkm
    gemm_k<0><<<gB256, 256>>>(cat, 512, Wkm, 256, vb, 256, 256, nullptr, nullptr, nullptr, 0);
    // attention -> c into cat[:,256:512]
    attn_k<<<Bsz, 256, 204800>>>(nb_rel, delta_t, maskp, vb, lg, cat);
    // gg = [m_init,c] @ [Wg_top; Wm@Wg_bot] + bg
    gemm_k<0><<<gB256, 256>>>(cat, 512, Wgf, 256, ggb, 256, 512, bg, nullptr, nullptr, 0);
    // m_out = sigmoid(gg)*tanh(c@Wmt + bt) + (1-sigmoid(gg))*m_init
    gemm_k<2><<<gB256, 256>>>(cat + 256, 512, Wmt, 256, mob, 256, 256, bt, ggb, cat, 512);
    // y = m_out @ Wo + bo
    gemm_k<0><<<gB512, 256>>>(mob, 256, Wo, 512, yb, 512, 256, bo, nullptr, nullptr, 0);
    // layernorm -> out
    ln_k<<<Bsz, 256>>>(yb, lng, lnb, out);
}

// round 2
// speedup vs baseline: 1.5588x; 1.5588x over previous
#include <cuda_runtime.h>
#include <math.h>

#define Bsz  2048
#define Nn_  200
#define FILLV (-10000.0f)

// ---------------- device scratch ----------------
__device__ float g_WmT[256 * 256];
__device__ float g_T1 [256 * 256];        // Wi @ Wk
__device__ float g_Wkm[256 * 256];        // Wk @ Wm^T
__device__ float g_Wik[256 * 256];        // Wi @ Wk @ Wm^T
__device__ float g_Wgfull[512 * 256];     // [Wg_top ; Wm @ Wg_bot]
__device__ float g_Wmt[256 * 256];        // Wm @ Wt
__device__ float g_bik[256];              // bi @ Wkm
__device__ float g_cat[Bsz * 512];        // [:,0:256]=m_init  [:,256:512]=c
__device__ float g_v  [Bsz * 256];
__device__ float g_mo [Bsz * 256];
__device__ float g_y  [Bsz * 512];
__device__ int   g_flags[4];

// ---------------- cp.async helpers ----------------
__device__ __forceinline__ void cp16(void* dst, const void* src) {
    unsigned sa = (unsigned)__cvta_generic_to_shared(dst);
    asm volatile("cp.async.cg.shared.global [%0], [%1], 16;" ::"r"(sa), "l"(src) : "memory");
}
__device__ __forceinline__ void cp_commit() { asm volatile("cp.async.commit_group;" ::: "memory"); }
__device__ __forceinline__ void cp_wait0()  { asm volatile("cp.async.wait_group 0;" ::: "memory"); }
__device__ __forceinline__ void cp_wait1()  { asm volatile("cp.async.wait_group 1;" ::: "memory"); }
__device__ __forceinline__ void cp_wait_n(int n) {
    switch (n) {
        case 0: asm volatile("cp.async.wait_group 0;" ::: "memory"); break;
        case 1: asm volatile("cp.async.wait_group 1;" ::: "memory"); break;
        case 2: asm volatile("cp.async.wait_group 2;" ::: "memory"); break;
        case 3: asm volatile("cp.async.wait_group 3;" ::: "memory"); break;
        default: asm volatile("cp.async.wait_group 4;" ::: "memory"); break;
    }
}

// ---------------- prep: transpose Wm, copy Wg top half, zero flags ----------------
__global__ void prep_k(const float* __restrict__ Wm, const float* __restrict__ Wg) {
    int bid = blockIdx.x, t = threadIdx.x;
    if (bid == 0 && t < 4) g_flags[t] = 0;
    if (bid < 256) {
        g_WmT[bid * 256 + t] = Wm[t * 256 + bid];
    } else {
        int idx = (bid - 256) * 1024 + t * 4;    // 64 blocks cover 65536 floats
        *(float4*)&g_Wgfull[idx] = *(const float4*)&Wg[idx];
    }
}

// ---------------- mask layout detection (parallel) ----------------
__global__ void detect_k(const unsigned* __restrict__ p) {
    unsigned m = 0;
    for (int i = blockIdx.x * 256 + threadIdx.x; i < 102400; i += 64 * 256) {
        unsigned wv = p[i];
        if (wv & 0x000000FFu) m |= 1;
        if (wv & 0x0000FF00u) m |= 2;
        if (wv & 0x00FF0000u) m |= 4;
        if (wv & 0xFF000000u) m |= 8;
    }
#pragma unroll
    for (int o = 16; o > 0; o >>= 1) m |= __shfl_down_sync(0xffffffffu, m, o);
    if ((threadIdx.x & 31) == 0 && m) {
        if (m & 1) atomicOr(&g_flags[0], 1);
        if (m & 2) atomicOr(&g_flags[1], 1);
        if (m & 4) atomicOr(&g_flags[2], 1);
        if (m & 8) atomicOr(&g_flags[3], 1);
    }
}

// ---------------- double-buffered 64x64x16 fp32 mainloop ----------------
__device__ __forceinline__ void gemm_mainloop(
    const float* __restrict__ A, int lda,
    const float* __restrict__ B, int ldb,
    int K, int m0, int n0, float acc[4][4])
{
    __shared__ float As[2][64][20];
    __shared__ float Bs[2][16][68];
    const int t = threadIdx.x;
    const int arow = t >> 2, ac4 = (t & 3) * 4;
    const int brow = t >> 4, bc4 = (t & 15) * 4;
    const int tx = t & 15, ty = t >> 4;
    const float* Ag = A + (size_t)(m0 + arow) * lda + ac4;
    const float* Bg = B + (size_t)brow * ldb + n0 + bc4;

    cp16(&As[0][arow][ac4], Ag);
    cp16(&Bs[0][brow][bc4], Bg);
    cp_commit();
    const int nIt = K / 16;
    for (int it = 0; it < nIt; ++it) {
        const int st = it & 1;
        if (it + 1 < nIt) {
            cp16(&As[st ^ 1][arow][ac4], Ag + (it + 1) * 16);
            cp16(&Bs[st ^ 1][brow][bc4], Bg + (size_t)(it + 1) * 16 * ldb);
            cp_commit();
            cp_wait1();
        } else cp_wait0();
        __syncthreads();
#pragma unroll
        for (int k = 0; k < 16; k++) {
            float a0 = As[st][ty * 4 + 0][k];
            float a1 = As[st][ty * 4 + 1][k];
            float a2 = As[st][ty * 4 + 2][k];
            float a3 = As[st][ty * 4 + 3][k];
            float4 b = *(const float4*)&Bs[st][k][tx * 4];
            acc[0][0] = fmaf(a0, b.x, acc[0][0]); acc[0][1] = fmaf(a0, b.y, acc[0][1]);
            acc[0][2] = fmaf(a0, b.z, acc[0][2]); acc[0][3] = fmaf(a0, b.w, acc[0][3]);
            acc[1][0] = fmaf(a1, b.x, acc[1][0]); acc[1][1] = fmaf(a1, b.y, acc[1][1]);
            acc[1][2] = fmaf(a1, b.z, acc[1][2]); acc[1][3] = fmaf(a1, b.w, acc[1][3]);
            acc[2][0] = fmaf(a2, b.x, acc[2][0]); acc[2][1] = fmaf(a2, b.y, acc[2][1]);
            acc[2][2] = fmaf(a2, b.z, acc[2][2]); acc[2][3] = fmaf(a2, b.w, acc[2][3]);
            acc[3][0] = fmaf(a3, b.x, acc[3][0]); acc[3][1] = fmaf(a3, b.y, acc[3][1]);
            acc[3][2] = fmaf(a3, b.z, acc[3][2]); acc[3][3] = fmaf(a3, b.w, acc[3][3]);
        }
        __syncthreads();
    }
}

#define ZERO44(a) {_Pragma("unroll") for(int i=0;i<4;i++) _Pragma("unroll") for(int j=0;j<4;j++) a[i][j]=0.f;}

// ---------------- precompute stage 1: three independent 256^3 GEMMs ----------------
__global__ void __launch_bounds__(256) pre1_k(
    const float* __restrict__ Wi, const float* __restrict__ Wk,
    const float* __restrict__ Wm, const float* __restrict__ Wg,
    const float* __restrict__ Wt)
{
    const float* A; const float* B; float* C;
    if (blockIdx.z == 0)      { A = Wi; B = Wk;         C = g_T1; }
    else if (blockIdx.z == 1) { A = Wm; B = Wg + 65536; C = g_Wgfull + 65536; }
    else                      { A = Wm; B = Wt;         C = g_Wmt; }
    float acc[4][4]; ZERO44(acc);
    int m0 = blockIdx.y * 64, n0 = blockIdx.x * 64;
    gemm_mainloop(A, 256, B, 256, 256, m0, n0, acc);
    const int tx = threadIdx.x & 15, ty = threadIdx.x >> 4;
#pragma unroll
    for (int i = 0; i < 4; i++)
#pragma unroll
        for (int j = 0; j < 4; j++)
            C[(size_t)(m0 + ty * 4 + i) * 256 + n0 + tx * 4 + j] = acc[i][j];
}

// ---------------- precompute stage 2: Wkm = Wk@WmT, Wik = T1@WmT ----------------
__global__ void __launch_bounds__(256) pre2_k(const float* __restrict__ Wk) {
    const float* A; float* C;
    if (blockIdx.z == 0) { A = Wk;   C = g_Wkm; }
    else                 { A = g_T1; C = g_Wik; }
    float acc[4][4]; ZERO44(acc);
    int m0 = blockIdx.y * 64, n0 = blockIdx.x * 64;
    gemm_mainloop(A, 256, g_WmT, 256, 256, m0, n0, acc);
    const int tx = threadIdx.x & 15, ty = threadIdx.x >> 4;
#pragma unroll
    for (int i = 0; i < 4; i++)
#pragma unroll
        for (int j = 0; j < 4; j++)
            C[(size_t)(m0 + ty * 4 + i) * 256 + n0 + tx * 4 + j] = acc[i][j];
}

// ---------------- precompute stage 3: bik = bi @ Wkm ----------------
__global__ void pre3_k(const float* __restrict__ bi) {
    int j = threadIdx.x;
    float s = 0.f;
#pragma unroll 4
    for (int e = 0; e < 256; e++) s = fmaf(bi[e], g_Wkm[e * 256 + j], s);
    g_bik[j] = s;
}

// ---------------- GEMM1: [m_init | v] = r_emb @ [Wi | Wik] + [bi | bik] ----------------
__global__ void __launch_bounds__(256) gemm1_k(
    const float* __restrict__ r_emb, const float* __restrict__ Wi,
    const float* __restrict__ bi)
{
    int m0 = blockIdx.y * 64, n0 = blockIdx.x * 64;
    const float* B; int nb0;
    if (n0 < 256) { B = Wi;    nb0 = n0; }
    else          { B = g_Wik; nb0 = n0 - 256; }
    float acc[4][4]; ZERO44(acc);
    gemm_mainloop(r_emb, 256, B, 256, 256, m0, nb0, acc);
    const int tx = threadIdx.x & 15, ty = threadIdx.x >> 4;
#pragma unroll
    for (int i = 0; i < 4; i++) {
        int gm = m0 + ty * 4 + i;
#pragma unroll
        for (int j = 0; j < 4; j++) {
            int gn = n0 + tx * 4 + j;
            if (gn < 256) g_cat[(size_t)gm * 512 + gn] = acc[i][j] + bi[gn];
            else          g_v[(size_t)gm * 256 + gn - 256] = acc[i][j] + g_bik[gn - 256];
        }
    }
}

// ---------------- attention: one CTA per batch, pipelined tile load ----------------
__global__ void __launch_bounds__(256) attn_k(
    const float* __restrict__ nb_rel,
    const float* __restrict__ delta_t,
    const void*  __restrict__ maskp,
    const float* __restrict__ lgam)
{
    extern __shared__ float TILE[];          // 200x256 fp32
    __shared__ float SA[256];
    __shared__ float RED[256];
    __shared__ int   IRED[256];
    const int t = threadIdx.x, b = blockIdx.x;
    const int w = t >> 5, l = t & 31;

    // warp w owns rows 25w..25w+24, loaded as 5 groups of 5 rows
    const float4* g4 = (const float4*)(nb_rel + (size_t)b * Nn_ * 256);
    float4* s4 = (float4*)TILE;
    for (int g = 0; g < 5; g++) {
#pragma unroll
        for (int j = 0; j < 5; j++) {
            int r = w * 25 + g * 5 + j;
            cp16(&s4[r * 64 + l],      &g4[r * 64 + l]);
            cp16(&s4[r * 64 + 32 + l], &g4[r * 64 + 32 + l]);
        }
        cp_commit();
    }

    float vr[8];
#pragma unroll
    for (int k = 0; k < 8; k++) vr[k] = g_v[(size_t)b * 256 + k * 32 + l];
    float gamma = expf(lgam[0]);
    int f0 = g_flags[0], f1 = g_flags[1], f2 = g_flags[2], f3 = g_flags[3];
    int mode = f1 ? 0 : ((f2 | f3) ? 2 : (f0 ? 1 : 0));

    // sem dots per group as data lands (no cross-warp dependency)
    for (int g = 0; g < 5; g++) {
        cp_wait_n(4 - g);
        __syncwarp();
#pragma unroll
        for (int j = 0; j < 5; j++) {
            int n = w * 25 + g * 5 + j;
            float s = 0.f;
#pragma unroll
            for (int k = 0; k < 8; k++)
                s = fmaf(TILE[n * 256 + k * 32 + l], vr[k], s);
#pragma unroll
            for (int o = 16; o > 0; o >>= 1) s += __shfl_down_sync(0xffffffffu, s, o);
            if (l == 0) SA[n] = s * 0.0625f;
        }
    }
    __syncthreads();

    // mask + decay + softmax
    int m = 0;
    float av = FILLV;
    if (t < Nn_) {
        size_t mi = (size_t)b * Nn_ + t;
        if (mode == 0)      m = ((const unsigned char*)maskp)[mi] != 0;
        else if (mode == 1) m = ((const int*)maskp)[mi] != 0;
        else                m = (((const float*)maskp)[mi] != 0.f);
        if (m) {
            float term = fmaxf(-gamma * fmaxf(delta_t[mi], 0.f), -10.f);
            av = SA[t] + term;
        }
    }
    IRED[t] = m;
    __syncthreads();
    for (int s = 128; s > 0; s >>= 1) { if (t < s) IRED[t] |= IRED[t + s]; __syncthreads(); }
    int anyv = IRED[0];
    __syncthreads();
    if (!anyv && t < Nn_) av = 0.f;

    RED[t] = av;
    __syncthreads();
    for (int s = 128; s > 0; s >>= 1) { if (t < s) RED[t] = fmaxf(RED[t], RED[t + s]); __syncthreads(); }
    float mx = RED[0];
    __syncthreads();
    float ex = (t < Nn_) ? expf(av - mx) : 0.f;
    RED[t] = ex;
    __syncthreads();
    for (int s = 128; s > 0; s >>= 1) { if (t < s) RED[t] += RED[t + s]; __syncthreads(); }
    float inv = 1.f / RED[0];
    __syncthreads();
    if (t < Nn_) SA[t] = ex * inv;
    __syncthreads();

    // c[r] = sum_n w[n] * tile[n][r]
    float c0 = 0.f, c1 = 0.f;
#pragma unroll 4
    for (int n = 0; n < Nn_; n += 2) {
        c0 = fmaf(SA[n],     TILE[n * 256 + t],       c0);
        c1 = fmaf(SA[n + 1], TILE[(n + 1) * 256 + t], c1);
    }
    g_cat[(size_t)b * 512 + 256 + t] = c0 + c1;
}

// ---------------- GEMM2: gg = cat@Wgf (K=512), tpre = c@Wmt (K=256), gate epilogue ----------------
__global__ void __launch_bounds__(256) gemm2_k(
    const float* __restrict__ bg, const float* __restrict__ bt)
{
    __shared__ float As [2][64][20];
    __shared__ float B1s[2][16][68];
    __shared__ float B2s[2][16][68];
    const int t = threadIdx.x;
    const int arow = t >> 2, ac4 = (t & 3) * 4;
    const int brow = t >> 4, bc4 = (t & 15) * 4;
    const int tx = t & 15, ty = t >> 4;
    const int m0 = blockIdx.y * 64, n0 = blockIdx.x * 64;

    const float* Ag  = g_cat    + (size_t)(m0 + arow) * 512 + ac4;
    const float* B1g = g_Wgfull + (size_t)brow * 256 + n0 + bc4;
    const float* B2g = g_Wmt    + (size_t)brow * 256 + n0 + bc4;

    float accg[4][4], acct[4][4];
    ZERO44(accg); ZERO44(acct);

    // issue stage 0
    cp16(&As[0][arow][ac4], Ag);
    cp16(&B1s[0][brow][bc4], B1g);
    cp_commit();
    const int nIt = 32;   // K = 512
    for (int it = 0; it < nIt; ++it) {
        const int st = it & 1;
        if (it + 1 < nIt) {
            int kb = (it + 1) * 16;
            cp16(&As[st ^ 1][arow][ac4], Ag + kb);
            cp16(&B1s[st ^ 1][brow][bc4], B1g + (size_t)kb * 256);
            if (kb >= 256)
                cp16(&B2s[st ^ 1][brow][bc4], B2g + (size_t)(kb - 256) * 256);
            cp_commit();
            cp_wait1();
        } else cp_wait0();
        __syncthreads();
        if (it < 16) {
#pragma unroll
            for (int k = 0; k < 16; k++) {
                float a0 = As[st][ty * 4 + 0][k];
                float a1 = As[st][ty * 4 + 1][k];
                float a2 = As[st][ty * 4 + 2][k];
                float a3 = As[st][ty * 4 + 3][k];
                float4 b = *(const float4*)&B1s[st][k][tx * 4];
                accg[0][0] = fmaf(a0, b.x, accg[0][0]); accg[0][1] = fmaf(a0, b.y, accg[0][1]);
                accg[0][2] = fmaf(a0, b.z, accg[0][2]); accg[0][3] = fmaf(a0, b.w, accg[0][3]);
                accg[1][0] = fmaf(a1, b.x, accg[1][0]); accg[1][1] = fmaf(a1, b.y, accg[1][1]);
                accg[1][2] = fmaf(a1, b.z, accg[1][2]); accg[1][3] = fmaf(a1, b.w, accg[1][3]);
                accg[2][0] = fmaf(a2, b.x, accg[2][0]); accg[2][1] = fmaf(a2, b.y, accg[2][1]);
                accg[2][2] = fmaf(a2, b.z, accg[2][2]); accg[2][3] = fmaf(a2, b.w, accg[2][3]);
                accg[3][0] = fmaf(a3, b.x, accg[3][0]); accg[3][1] = fmaf(a3, b.y, accg[3][1]);
                accg[3][2] = fmaf(a3, b.z, accg[3][2]); accg[3][3] = fmaf(a3, b.w, accg[3][3]);
            }
        } else {
#pragma unroll
            for (int k = 0; k < 16; k++) {
                float a0 = As[st][ty * 4 + 0][k];
                float a1 = As[st][ty * 4 + 1][k];
                float a2 = As[st][ty * 4 + 2][k];
                float a3 = As[st][ty * 4 + 3][k];
                float4 b = *(const float4*)&B1s[st][k][tx * 4];
                float4 c = *(const float4*)&B2s[st][k][tx * 4];
                accg[0][0] = fmaf(a0, b.x, accg[0][0]); accg[0][1] = fmaf(a0, b.y, accg[0][1]);
                accg[0][2] = fmaf(a0, b.z, accg[0][2]); accg[0][3] = fmaf(a0, b.w, accg[0][3]);
                accg[1][0] = fmaf(a1, b.x, accg[1][0]); accg[1][1] = fmaf(a1, b.y, accg[1][1]);
                accg[1][2] = fmaf(a1, b.z, accg[1][2]); accg[1][3] = fmaf(a1, b.w, accg[1][3]);
                accg[2][0] = fmaf(a2, b.x, accg[2][0]); accg[2][1] = fmaf(a2, b.y, accg[2][1]);
                accg[2][2] = fmaf(a2, b.z, accg[2][2]); accg[2][3] = fmaf(a2, b.w, accg[2][3]);
                accg[3][0] = fmaf(a3, b.x, accg[3][0]); accg[3][1] = fmaf(a3, b.y, accg[3][1]);
                accg[3][2] = fmaf(a3, b.z, accg[3][2]); accg[3][3] = fmaf(a3, b.w, accg[3][3]);
                acct[0][0] = fmaf(a0, c.x, acct[0][0]); acct[0][1] = fmaf(a0, c.y, acct[0][1]);
                acct[0][2] = fmaf(a0, c.z, acct[0][2]); acct[0][3] = fmaf(a0, c.w, acct[0][3]);
                acct[1][0] = fmaf(a1, c.x, acct[1][0]); acct[1][1] = fmaf(a1, c.y, acct[1][1]);
                acct[1][2] = fmaf(a1, c.z, acct[1][2]); acct[1][3] = fmaf(a1, c.w, acct[1][3]);
                acct[2][0] = fmaf(a2, c.x, acct[2][0]); acct[2][1] = fmaf(a2, c.y, acct[2][1]);
                acct[2][2] = fmaf(a2, c.z, acct[2][2]); acct[2][3] = fmaf(a2, c.w, acct[2][3]);
                acct[3][0] = fmaf(a3, c.x, acct[3][0]); acct[3][1] = fmaf(a3, c.y, acct[3][1]);
                acct[3][2] = fmaf(a3, c.z, acct[3][2]); acct[3][3] = fmaf(a3, c.w, acct[3][3]);
            }
        }
        __syncthreads();
    }

#pragma unroll
    for (int i = 0; i < 4; i++) {
        int gm = m0 + ty * 4 + i;
#pragma unroll
        for (int j = 0; j < 4; j++) {
            int gn = n0 + tx * 4 + j;
            float gate = 1.f / (1.f + expf(-(accg[i][j] + bg[gn])));
            float th = tanhf(acct[i][j] + bt[gn]);
            g_mo[(size_t)gm * 256 + gn] = gate * th + (1.f - gate) * g_cat[(size_t)gm * 512 + gn];
        }
    }
}

// ---------------- GEMM3: y = m_out @ Wo + bo ----------------
__global__ void __launch_bounds__(256) gemm3_k(
    const float* __restrict__ Wo, const float* __restrict__ bo)
{
    int m0 = blockIdx.y * 64, n0 = blockIdx.x * 64;
    float acc[4][4]; ZERO44(acc);
    gemm_mainloop(g_mo, 256, Wo, 512, 256, m0, n0, acc);
    const int tx = threadIdx.x & 15, ty = threadIdx.x >> 4;
#pragma unroll
    for (int i = 0; i < 4; i++)
#pragma unroll
        for (int j = 0; j < 4; j++)
            g_y[(size_t)(m0 + ty * 4 + i) * 512 + n0 + tx * 4 + j] = acc[i][j] + bo[n0 + tx * 4 + j];
}

// ---------------- layernorm ----------------
__global__ void __launch_bounds__(256) ln_k(
    const float* __restrict__ g, const float* __restrict__ bta, float* __restrict__ out)
{
    __shared__ float RS[256], RQ[256];
    const int t = threadIdx.x, b = blockIdx.x;
    float a = g_y[(size_t)b * 512 + t];
    float c = g_y[(size_t)b * 512 + 256 + t];
    RS[t] = a + c;
    RQ[t] = a * a + c * c;
    __syncthreads();
    for (int s = 128; s > 0; s >>= 1) {
        if (t < s) { RS[t] += RS[t + s]; RQ[t] += RQ[t + s]; }
        __syncthreads();
    }
    float mu = RS[0] * (1.f / 512.f);
    float var = RQ[0] * (1.f / 512.f) - mu * mu;
    float inv = rsqrtf(var + 1e-5f);
    out[(size_t)b * 512 + t]       = (a - mu) * inv * g[t] + bta[t];
    out[(size_t)b * 512 + 256 + t] = (c - mu) * inv * g[t + 256] + bta[t + 256];
}

// ---------------- launch ----------------
extern "C" void kernel_launch(void* const* d_in, const int* in_sizes, int n_in,
                              void* d_out, int out_size) {
    const float* nb_rel  = (const float*)d_in[0];
    const float* delta_t = (const float*)d_in[1];
    const float* r_emb   = (const float*)d_in[2];
    const void*  maskp   = d_in[3];
    const float* Wi = (const float*)d_in[4];
    const float* bi = (const float*)d_in[5];
    const float* Wm = (const float*)d_in[6];
    const float* Wk = (const float*)d_in[7];
    const float* lg = (const float*)d_in[8];
    const float* Wg = (const float*)d_in[9];
    const float* bg = (const float*)d_in[10];
    const float* Wt = (const float*)d_in[11];
    const float* bt = (const float*)d_in[12];
    const float* Wo = (const float*)d_in[13];
    const float* bo = (const float*)d_in[14];
    const float* lng = (const float*)d_in[15];
    const float* lnb = (const float*)d_in[16];
    float* out = (float*)d_out;

    cudaFuncSetAttribute(attn_k, cudaFuncAttributeMaxDynamicSharedMemorySize, 204800);

    prep_k<<<320, 256>>>(Wm, Wg);
    detect_k<<<64, 256>>>((const unsigned*)maskp);
    pre1_k<<<dim3(4, 4, 3), 256>>>(Wi, Wk, Wm, Wg, Wt);
    pre2_k<<<dim3(4, 4, 2), 256>>>(Wk);
    pre3_k<<<1, 256>>>(bi);

    gemm1_k<<<dim3(8, 32), 256>>>(r_emb, Wi, bi);
    attn_k<<<Bsz, 256, 204800>>>(nb_rel, delta_t, maskp, lg);
    gemm2_k<<<dim3(4, 32), 256>>>(bg, bt);
    gemm3_k<<<dim3(8, 32), 256>>>(Wo, bo);
    ln_k<<<Bsz, 256>>>(lng, lnb, out);
}

// round 3
// speedup vs baseline: 1.7802x; 1.1420x over previous
#include <cuda_runtime.h>
#include <math.h>

#define Bsz  2048
#define Nn_  200
#define FILLV (-10000.0f)

// ---------------- device scratch ----------------
__device__ float g_WmT[256 * 256];
__device__ float g_Wkm[256 * 256];        // Wk @ Wm^T
__device__ float g_Wgfull[512 * 256];     // [Wg_top ; Wm @ Wg_bot]
__device__ float g_Wmt[256 * 256];        // Wm @ Wt
__device__ float g_cat[Bsz * 512];        // [:,0:256]=m_init  [:,256:512]=c
__device__ float g_v  [Bsz * 256];
__device__ float g_mo [Bsz * 256];
__device__ float g_y  [Bsz * 512];
__device__ int   g_flags[4];              // OR-only, idempotent across replays

// ---------------- cp.async helpers ----------------
__device__ __forceinline__ void cp16(void* dst, const void* src) {
    unsigned sa = (unsigned)__cvta_generic_to_shared(dst);
    asm volatile("cp.async.cg.shared.global [%0], [%1], 16;" ::"r"(sa), "l"(src) : "memory");
}
__device__ __forceinline__ void cp_commit() { asm volatile("cp.async.commit_group;" ::: "memory"); }
__device__ __forceinline__ void cp_wait0()  { asm volatile("cp.async.wait_group 0;" ::: "memory"); }
__device__ __forceinline__ void cp_wait1()  { asm volatile("cp.async.wait_group 1;" ::: "memory"); }
__device__ __forceinline__ void cp_wait_n(int n) {
    switch (n) {
        case 0: asm volatile("cp.async.wait_group 0;" ::: "memory"); break;
        case 1: asm volatile("cp.async.wait_group 1;" ::: "memory"); break;
        case 2: asm volatile("cp.async.wait_group 2;" ::: "memory"); break;
        case 3: asm volatile("cp.async.wait_group 3;" ::: "memory"); break;
        default: asm volatile("cp.async.wait_group 4;" ::: "memory"); break;
    }
}

#define ZERO44(a) {_Pragma("unroll") for(int i=0;i<4;i++) _Pragma("unroll") for(int j=0;j<4;j++) a[i][j]=0.f;}
#define FMA4(r, av, bv) { (r)[0]=fmaf((av),(bv).x,(r)[0]); (r)[1]=fmaf((av),(bv).y,(r)[1]); \
                          (r)[2]=fmaf((av),(bv).z,(r)[2]); (r)[3]=fmaf((av),(bv).w,(r)[3]); }

// vectorized 16-k compute: A smem [64][20] row-major (k inner), B smem [16][68]
__device__ __forceinline__ void compute16(
    const float (*__restrict__ A)[20], const float (*__restrict__ Bm)[68],
    int ty, int tx, float acc[4][4])
{
#pragma unroll
    for (int kq = 0; kq < 16; kq += 4) {
        float4 a[4], b[4];
#pragma unroll
        for (int i = 0; i < 4; i++) a[i] = *(const float4*)&A[ty * 4 + i][kq];
#pragma unroll
        for (int kk = 0; kk < 4; kk++) b[kk] = *(const float4*)&Bm[kq + kk][tx * 4];
#pragma unroll
        for (int i = 0; i < 4; i++) {
            FMA4(acc[i], a[i].x, b[0]);
            FMA4(acc[i], a[i].y, b[1]);
            FMA4(acc[i], a[i].z, b[2]);
            FMA4(acc[i], a[i].w, b[3]);
        }
    }
}

__device__ __forceinline__ void compute16_dual(
    const float (*__restrict__ A)[20], const float (*__restrict__ B1)[68],
    const float (*__restrict__ B2)[68],
    int ty, int tx, float accg[4][4], float acct[4][4])
{
#pragma unroll
    for (int kq = 0; kq < 16; kq += 4) {
        float4 a[4], b[4], c[4];
#pragma unroll
        for (int i = 0; i < 4; i++) a[i] = *(const float4*)&A[ty * 4 + i][kq];
#pragma unroll
        for (int kk = 0; kk < 4; kk++) {
            b[kk] = *(const float4*)&B1[kq + kk][tx * 4];
            c[kk] = *(const float4*)&B2[kq + kk][tx * 4];
        }
#pragma unroll
        for (int i = 0; i < 4; i++) {
            FMA4(accg[i], a[i].x, b[0]);
            FMA4(accg[i], a[i].y, b[1]);
            FMA4(accg[i], a[i].z, b[2]);
            FMA4(accg[i], a[i].w, b[3]);
            FMA4(acct[i], a[i].x, c[0]);
            FMA4(acct[i], a[i].y, c[1]);
            FMA4(acct[i], a[i].z, c[2]);
            FMA4(acct[i], a[i].w, c[3]);
        }
    }
}

// ---------------- double-buffered 64x64x16 fp32 mainloop ----------------
__device__ __forceinline__ void gemm_mainloop(
    const float* __restrict__ A, int lda,
    const float* __restrict__ B, int ldb,
    int K, int m0, int n0, float acc[4][4])
{
    __shared__ float As[2][64][20];
    __shared__ float Bs[2][16][68];
    const int t = threadIdx.x;
    const int arow = t >> 2, ac4 = (t & 3) * 4;
    const int brow = t >> 4, bc4 = (t & 15) * 4;
    const int tx = t & 15, ty = t >> 4;
    const float* Ag = A + (size_t)(m0 + arow) * lda + ac4;
    const float* Bg = B + (size_t)brow * ldb + n0 + bc4;

    cp16(&As[0][arow][ac4], Ag);
    cp16(&Bs[0][brow][bc4], Bg);
    cp_commit();
    const int nIt = K / 16;
    for (int it = 0; it < nIt; ++it) {
        const int st = it & 1;
        if (it + 1 < nIt) {
            cp16(&As[st ^ 1][arow][ac4], Ag + (it + 1) * 16);
            cp16(&Bs[st ^ 1][brow][bc4], Bg + (size_t)(it + 1) * 16 * ldb);
            cp_commit();
            cp_wait1();
        } else cp_wait0();
        __syncthreads();
        compute16(As[st], Bs[st], ty, tx, acc);
        __syncthreads();
    }
}

// ---------------- prep: transpose Wm, copy Wg top, detect mask layout ----------------
__global__ void prep_k(const float* __restrict__ Wm, const float* __restrict__ Wg,
                       const unsigned* __restrict__ mp) {
    int bid = blockIdx.x, t = threadIdx.x;
    if (bid < 256) {
        g_WmT[bid * 256 + t] = Wm[t * 256 + bid];
    } else if (bid < 320) {
        int idx = (bid - 256) * 1024 + t * 4;
        *(float4*)&g_Wgfull[idx] = *(const float4*)&Wg[idx];
    } else {
        unsigned m = 0;
        for (int i = (bid - 320) * 256 + t; i < 102400; i += 64 * 256) {
            unsigned wv = mp[i];
            if (wv & 0x000000FFu) m |= 1;
            if (wv & 0x0000FF00u) m |= 2;
            if (wv & 0x00FF0000u) m |= 4;
            if (wv & 0xFF000000u) m |= 8;
        }
#pragma unroll
        for (int o = 16; o > 0; o >>= 1) m |= __shfl_down_sync(0xffffffffu, m, o);
        if ((t & 31) == 0 && m) {
            if (m & 1) atomicOr(&g_flags[0], 1);
            if (m & 2) atomicOr(&g_flags[1], 1);
            if (m & 4) atomicOr(&g_flags[2], 1);
            if (m & 8) atomicOr(&g_flags[3], 1);
        }
    }
}

// ---------------- pre_all: m_init GEMM + 3 weight-fold GEMMs in one launch ----------------
// grid (4, 44): y<32 -> m_init tiles; 32..35 Wkm; 36..39 Wm@Wg_bot; 40..43 Wm@Wt
__global__ void __launch_bounds__(256) pre_all_k(
    const float* __restrict__ r_emb, const float* __restrict__ Wi,
    const float* __restrict__ bi, const float* __restrict__ Wk,
    const float* __restrict__ Wm, const float* __restrict__ Wg,
    const float* __restrict__ Wt)
{
    const int yy = blockIdx.y;
    const float* A; const float* B; float* C; int lda, ldc, m0;
    const float* bias = nullptr;
    if (yy < 32)      { A = r_emb; lda = 256; B = Wi;          C = g_cat;           ldc = 512; m0 = yy * 64; bias = bi; }
    else if (yy < 36) { A = Wk;    lda = 256; B = g_WmT;       C = g_Wkm;           ldc = 256; m0 = (yy - 32) * 64; }
    else if (yy < 40) { A = Wm;    lda = 256; B = Wg + 65536;  C = g_Wgfull + 65536; ldc = 256; m0 = (yy - 36) * 64; }
    else              { A = Wm;    lda = 256; B = Wt;          C = g_Wmt;           ldc = 256; m0 = (yy - 40) * 64; }
    const int n0 = blockIdx.x * 64;
    float acc[4][4]; ZERO44(acc);
    gemm_mainloop(A, lda, B, 256, 256, m0, n0, acc);
    const int tx = threadIdx.x & 15, ty = threadIdx.x >> 4;
#pragma unroll
    for (int i = 0; i < 4; i++) {
        int gm = m0 + ty * 4 + i;
#pragma unroll
        for (int j = 0; j < 4; j++) {
            int gn = n0 + tx * 4 + j;
            float v = acc[i][j];
            if (bias) v += bias[gn];
            C[(size_t)gm * ldc + gn] = v;
        }
    }
}

// ---------------- gemm1b: v = m_init @ Wkm ----------------
__global__ void __launch_bounds__(256) gemm1b_k() {
    int m0 = blockIdx.y * 64, n0 = blockIdx.x * 64;
    float acc[4][4]; ZERO44(acc);
    gemm_mainloop(g_cat, 512, g_Wkm, 256, 256, m0, n0, acc);
    const int tx = threadIdx.x & 15, ty = threadIdx.x >> 4;
#pragma unroll
    for (int i = 0; i < 4; i++)
#pragma unroll
        for (int j = 0; j < 4; j++)
            g_v[(size_t)(m0 + ty * 4 + i) * 256 + n0 + tx * 4 + j] = acc[i][j];
}

// ---------------- attention: one CTA per batch, pipelined tile load ----------------
__global__ void __launch_bounds__(256) attn_k(
    const float* __restrict__ nb_rel,
    const float* __restrict__ delta_t,
    const void*  __restrict__ maskp,
    const float* __restrict__ lgam)
{
    extern __shared__ float TILE[];          // 200x256 fp32
    __shared__ float SA[256];
    __shared__ float RED[256];
    __shared__ int   IRED[256];
    const int t = threadIdx.x, b = blockIdx.x;
    const int w = t >> 5, l = t & 31;

    const float4* g4 = (const float4*)(nb_rel + (size_t)b * Nn_ * 256);
    float4* s4 = (float4*)TILE;
    for (int g = 0; g < 5; g++) {
#pragma unroll
        for (int j = 0; j < 5; j++) {
            int r = w * 25 + g * 5 + j;
            cp16(&s4[r * 64 + l],      &g4[r * 64 + l]);
            cp16(&s4[r * 64 + 32 + l], &g4[r * 64 + 32 + l]);
        }
        cp_commit();
    }

    float vr[8];
#pragma unroll
    for (int k = 0; k < 8; k++) vr[k] = g_v[(size_t)b * 256 + k * 32 + l];
    float gamma = expf(lgam[0]);
    int f0 = g_flags[0], f1 = g_flags[1], f2 = g_flags[2], f3 = g_flags[3];
    int mode = f1 ? 0 : ((f2 | f3) ? 2 : (f0 ? 1 : 0));

    for (int g = 0; g < 5; g++) {
        cp_wait_n(4 - g);
        __syncwarp();
#pragma unroll
        for (int j = 0; j < 5; j++) {
            int n = w * 25 + g * 5 + j;
            float s = 0.f;
#pragma unroll
            for (int k = 0; k < 8; k++)
                s = fmaf(TILE[n * 256 + k * 32 + l], vr[k], s);
#pragma unroll
            for (int o = 16; o > 0; o >>= 1) s += __shfl_down_sync(0xffffffffu, s, o);
            if (l == 0) SA[n] = s * 0.0625f;
        }
    }
    __syncthreads();

    int m = 0;
    float av = FILLV;
    if (t < Nn_) {
        size_t mi = (size_t)b * Nn_ + t;
        if (mode == 0)      m = ((const unsigned char*)maskp)[mi] != 0;
        else if (mode == 1) m = ((const int*)maskp)[mi] != 0;
        else                m = (((const float*)maskp)[mi] != 0.f);
        if (m) {
            float term = fmaxf(-gamma * fmaxf(delta_t[mi], 0.f), -10.f);
            av = SA[t] + term;
        }
    }
    IRED[t] = m;
    __syncthreads();
    for (int s = 128; s > 0; s >>= 1) { if (t < s) IRED[t] |= IRED[t + s]; __syncthreads(); }
    int anyv = IRED[0];
    __syncthreads();
    if (!anyv && t < Nn_) av = 0.f;

    RED[t] = av;
    __syncthreads();
    for (int s = 128; s > 0; s >>= 1) { if (t < s) RED[t] = fmaxf(RED[t], RED[t + s]); __syncthreads(); }
    float mx = RED[0];
    __syncthreads();
    float ex = (t < Nn_) ? expf(av - mx) : 0.f;
    RED[t] = ex;
    __syncthreads();
    for (int s = 128; s > 0; s >>= 1) { if (t < s) RED[t] += RED[t + s]; __syncthreads(); }
    float inv = 1.f / RED[0];
    __syncthreads();
    if (t < Nn_) SA[t] = ex * inv;
    __syncthreads();

    float c0 = 0.f, c1 = 0.f;
#pragma unroll 4
    for (int n = 0; n < Nn_; n += 2) {
        c0 = fmaf(SA[n],     TILE[n * 256 + t],       c0);
        c1 = fmaf(SA[n + 1], TILE[(n + 1) * 256 + t], c1);
    }
    g_cat[(size_t)b * 512 + 256 + t] = c0 + c1;
}

// ---------------- GEMM2: gg = cat@Wgf (K=512) & t = c@Wmt (K=256), gate epilogue ----------------
__global__ void __launch_bounds__(256) gemm2_k(
    const float* __restrict__ bg, const float* __restrict__ bt)
{
    __shared__ float As [2][64][20];
    __shared__ float B1s[2][16][68];
    __shared__ float B2s[2][16][68];
    const int t = threadIdx.x;
    const int arow = t >> 2, ac4 = (t & 3) * 4;
    const int brow = t >> 4, bc4 = (t & 15) * 4;
    const int tx = t & 15, ty = t >> 4;
    const int m0 = blockIdx.y * 64, n0 = blockIdx.x * 64;

    const float* Ag  = g_cat    + (size_t)(m0 + arow) * 512 + ac4;
    const float* B1g = g_Wgfull + (size_t)brow * 256 + n0 + bc4;
    const float* B2g = g_Wmt    + (size_t)brow * 256 + n0 + bc4;

    float accg[4][4], acct[4][4];
    ZERO44(accg); ZERO44(acct);

    cp16(&As[0][arow][ac4], Ag);
    cp16(&B1s[0][brow][bc4], B1g);
    cp_commit();
    const int nIt = 32;
    for (int it = 0; it < nIt; ++it) {
        const int st = it & 1;
        if (it + 1 < nIt) {
            int kb = (it + 1) * 16;
            cp16(&As[st ^ 1][arow][ac4], Ag + kb);
            cp16(&B1s[st ^ 1][brow][bc4], B1g + (size_t)kb * 256);
            if (kb >= 256)
                cp16(&B2s[st ^ 1][brow][bc4], B2g + (size_t)(kb - 256) * 256);
            cp_commit();
            cp_wait1();
        } else cp_wait0();
        __syncthreads();
        if (it < 16) compute16(As[st], B1s[st], ty, tx, accg);
        else         compute16_dual(As[st], B1s[st], B2s[st], ty, tx, accg, acct);
        __syncthreads();
    }

#pragma unroll
    for (int i = 0; i < 4; i++) {
        int gm = m0 + ty * 4 + i;
#pragma unroll
        for (int j = 0; j < 4; j++) {
            int gn = n0 + tx * 4 + j;
            float gate = 1.f / (1.f + expf(-(accg[i][j] + bg[gn])));
            float th = tanhf(acct[i][j] + bt[gn]);
            g_mo[(size_t)gm * 256 + gn] = gate * th + (1.f - gate) * g_cat[(size_t)gm * 512 + gn];
        }
    }
}

// ---------------- GEMM3: y = m_out @ Wo + bo ----------------
__global__ void __launch_bounds__(256) gemm3_k(
    const float* __restrict__ Wo, const float* __restrict__ bo)
{
    int m0 = blockIdx.y * 64, n0 = blockIdx.x * 64;
    float acc[4][4]; ZERO44(acc);
    gemm_mainloop(g_mo, 256, Wo, 512, 256, m0, n0, acc);
    const int tx = threadIdx.x & 15, ty = threadIdx.x >> 4;
#pragma unroll
    for (int i = 0; i < 4; i++)
#pragma unroll
        for (int j = 0; j < 4; j++)
            g_y[(size_t)(m0 + ty * 4 + i) * 512 + n0 + tx * 4 + j] = acc[i][j] + bo[n0 + tx * 4 + j];
}

// ---------------- layernorm ----------------
__global__ void __launch_bounds__(256) ln_k(
    const float* __restrict__ g, const float* __restrict__ bta, float* __restrict__ out)
{
    __shared__ float RS[256], RQ[256];
    const int t = threadIdx.x, b = blockIdx.x;
    float a = g_y[(size_t)b * 512 + t];
    float c = g_y[(size_t)b * 512 + 256 + t];
    RS[t] = a + c;
    RQ[t] = a * a + c * c;
    __syncthreads();
    for (int s = 128; s > 0; s >>= 1) {
        if (t < s) { RS[t] += RS[t + s]; RQ[t] += RQ[t + s]; }
        __syncthreads();
    }
    float mu = RS[0] * (1.f / 512.f);
    float var = RQ[0] * (1.f / 512.f) - mu * mu;
    float inv = rsqrtf(var + 1e-5f);
    out[(size_t)b * 512 + t]       = (a - mu) * inv * g[t] + bta[t];
    out[(size_t)b * 512 + 256 + t] = (c - mu) * inv * g[t + 256] + bta[t + 256];
}

// ---------------- launch ----------------
extern "C" void kernel_launch(void* const* d_in, const int* in_sizes, int n_in,
                              void* d_out, int out_size) {
    const float* nb_rel  = (const float*)d_in[0];
    const float* delta_t = (const float*)d_in[1];
    const float* r_emb   = (const float*)d_in[2];
    const void*  maskp   = d_in[3];
    const float* Wi = (const float*)d_in[4];
    const float* bi = (const float*)d_in[5];
    const float* Wm = (const float*)d_in[6];
    const float* Wk = (const float*)d_in[7];
    const float* lg = (const float*)d_in[8];
    const float* Wg = (const float*)d_in[9];
    const float* bg = (const float*)d_in[10];
    const float* Wt = (const float*)d_in[11];
    const float* bt = (const float*)d_in[12];
    const float* Wo = (const float*)d_in[13];
    const float* bo = (const float*)d_in[14];
    const float* lng = (const float*)d_in[15];
    const float* lnb = (const float*)d_in[16];
    float* out = (float*)d_out;

    cudaFuncSetAttribute(attn_k, cudaFuncAttributeMaxDynamicSharedMemorySize, 204800);

    prep_k<<<384, 256>>>(Wm, Wg, (const unsigned*)maskp);
    pre_all_k<<<dim3(4, 44), 256>>>(r_emb, Wi, bi, Wk, Wm, Wg, Wt);
    gemm1b_k<<<dim3(4, 32), 256>>>();
    attn_k<<<Bsz, 256, 204800>>>(nb_rel, delta_t, maskp, lg);
    gemm2_k<<<dim3(4, 32), 256>>>(bg, bt);
    gemm3_k<<<dim3(8, 32), 256>>>(Wo, bo);
    ln_k<<<Bsz, 256>>>(lng, lnb, out);
}